// round 6
// baseline (speedup 1.0000x reference)
#include <cuda_runtime.h>
#include <cuda_bf16.h>
#include <cuda_fp16.h>
#include <math.h>

#define NN 10000
#define EE 20000
#define BB 400

// ---------------- device scratch (static allocation only) ----------------
__device__ __half g_ewh[(size_t)EE * 4096]; // 163.8 MB edge-conditioned weights (fp16)
__device__ float g_he[EE * 64];             // edge hidden (MLP layer 1)
__device__ float g_out[NN * 64];            // node state (out == h)
__device__ float g_agg[NN * 64];            // scatter accumulator (kept zeroed)
__device__ float g_gi[NN * 192];            // GRU input gates
__device__ float g_gh[NN * 192];            // GRU hidden gates
__device__ float g_cnt[NN];
__device__ int   g_src[EE];
__device__ int   g_dst[EE];
__device__ int   g_batch[NN];
__device__ int   g_off[BB + 1];
__device__ float g_e[NN];
__device__ int   g_is64;

__device__ __forceinline__ float sigf(float x) { return 1.0f / (1.0f + expf(-x)); }

__device__ __forceinline__ float tf32r(float x) {
    unsigned int u;
    asm("cvt.rna.tf32.f32 %0, %1;" : "=r"(u) : "f"(x));
    return __uint_as_float(u);
}

#define MMA_TF32(C, A0, A1, A2, A3, B0, B1)                                          \
    asm volatile(                                                                    \
        "mma.sync.aligned.m16n8k8.row.col.f32.tf32.tf32.f32 "                        \
        "{%0,%1,%2,%3}, {%4,%5,%6,%7}, {%8,%9}, {%0,%1,%2,%3};"                      \
        : "+f"(C[0]), "+f"(C[1]), "+f"(C[2]), "+f"(C[3])                             \
        : "r"(A0), "r"(A1), "r"(A2), "r"(A3), "r"(B0), "r"(B1))

// ---------------- setup: dtype detect + zero cnt ----------------
__global__ void k_detect(const void* ei) {
    // int64 little-endian: odd 32-bit words (high halves) all zero.
    // int32: odd words are random node indices in [0,10000): P(all zero) ~ 0.
    if (blockIdx.x == 0 && threadIdx.x == 0) {
        const unsigned int* w = (const unsigned int*)ei;
        int all0 = 1;
        for (int i = 0; i < 127; i++)
            if (w[1 + 314 * i] != 0u) { all0 = 0; break; }
        g_is64 = all0;
    }
    int i = blockIdx.x * 256 + threadIdx.x;      // grid 40 => 10240 >= NN
    if (i < NN) g_cnt[i] = 0.0f;
}

// convert indices, count in-degree, zero agg
__global__ void k_convert(const void* ei, const void* bt) {
    int i = blockIdx.x * blockDim.x + threadIdx.x;
    int stride = gridDim.x * blockDim.x;
    int is64 = g_is64;
    for (int e = i; e < EE; e += stride) {
        int s, d;
        if (is64) {
            const long long* p = (const long long*)ei;
            s = (int)p[e]; d = (int)p[EE + e];
        } else {
            const int* p = (const int*)ei;
            s = p[e]; d = p[EE + e];
        }
        g_src[e] = s; g_dst[e] = d;
        atomicAdd(&g_cnt[d], 1.0f);             // g_cnt zeroed by k_detect (prior launch)
    }
    for (int n = i; n < NN; n += stride) {
        int b;
        if (is64) b = (int)((const long long*)bt)[n];
        else      b = ((const int*)bt)[n];
        g_batch[n] = b;
    }
    for (int j = i; j < NN * 64; j += stride) g_agg[j] = 0.0f;
}

// ---------------- fused projections + segment offsets -----------------------
// blocks [0,2500): node proj; [2500,7500): edge proj; [7500,7502): offsets
__global__ void k_proj(const float* __restrict__ x, const float* __restrict__ Wn,
                       const float* __restrict__ bn, const float* __restrict__ ea,
                       const float* __restrict__ We, const float* __restrict__ be) {
    __shared__ float Ws[64 * 33];
    int tid = threadIdx.x;
    if (blockIdx.x < 2500) {
        // node: out = relu(x @ Wn^T + bn), x[N,32]
        for (int idx = tid; idx < 64 * 32; idx += 256)
            Ws[(idx >> 5) * 33 + (idx & 31)] = Wn[idx];
        __syncthreads();
        int i = blockIdx.x * 256 + tid;          // 2500*256 == N*64 exact
        int n = i >> 6, j = i & 63;
        const float* xr = x + n * 32;
        float acc = bn[j];
#pragma unroll
        for (int k = 0; k < 32; k++) acc += xr[k] * Ws[j * 33 + k];
        g_out[i] = fmaxf(acc, 0.0f);
    } else if (blockIdx.x < 7500) {
        // edge: he = relu(ea @ We^T + be), ea[E,16]
        for (int idx = tid; idx < 64 * 16; idx += 256)
            Ws[(idx >> 4) * 17 + (idx & 15)] = We[idx];
        __syncthreads();
        int i = (blockIdx.x - 2500) * 256 + tid; // 5000*256 == E*64 exact
        int e = i >> 6, j = i & 63;
        const float* er = ea + e * 16;
        float acc = be[j];
#pragma unroll
        for (int k = 0; k < 16; k++) acc += er[k] * Ws[j * 17 + k];
        g_he[i] = fmaxf(acc, 0.0f);
    } else {
        // segment offsets via binary search on sorted batch
        int b = (blockIdx.x - 7500) * 256 + tid;
        if (b <= BB) {
            int lo = 0, hi = NN;
            while (lo < hi) {
                int mid = (lo + hi) >> 1;
                if (g_batch[mid] < b) lo = mid + 1; else hi = mid;
            }
            g_off[b] = lo;
        }
    }
}

// ---------------- ew GEMM: g_ewh[E,4096] = he @ W_e2^T + b_e2 (tf32 x1, fp16 out)
// Block: 128 M-rows x 128 N-cols (two sequential 64-col B tiles over one A tile)
// to halve L2 A-tile re-reads. grid (157, 32).
#define EW_SMEM (((128 * 68) + (64 * 72)) * 4)

__global__ void __launch_bounds__(256) k_ewgemm(const float* __restrict__ W,
                                                const float* __restrict__ bias) {
    extern __shared__ float sm[];
    float* As = sm;                    // [128][68]
    float* Bs = sm + 128 * 68;         // [64 k][72 n]

    const int tid = threadIdx.x;
    const int m0 = blockIdx.x * 128;
    const int warp = tid >> 5, lane = tid & 31;
    const int gid = lane >> 2, tg = lane & 3;
    const int ar = warp * 16 + gid;
    const int r0 = m0 + ar;

    for (int idx = tid; idx < 128 * 64; idx += 256) {
        int r = idx >> 6, c = idx & 63;
        int gr = m0 + r;
        float v = (gr < EE) ? g_he[gr * 64 + c] : 0.0f;
        As[r * 68 + c] = tf32r(v);
    }

    for (int half = 0; half < 2; half++) {
        const int n0 = blockIdx.y * 128 + half * 64;
        __syncthreads();               // A ready (half 0); prior compute done (half 1)
        for (int idx = tid; idx < 64 * 64; idx += 256) {
            int n = idx >> 6, k = idx & 63;
            Bs[k * 72 + n] = tf32r(W[(n0 + n) * 64 + k]);
        }
        __syncthreads();

        float c[8][4];
#pragma unroll
        for (int i = 0; i < 8; i++)
#pragma unroll
            for (int j = 0; j < 4; j++) c[i][j] = 0.0f;

#pragma unroll
        for (int ks = 0; ks < 8; ks++) {
            int k0 = ks * 8 + tg, k1 = k0 + 4;
            unsigned int a0 = __float_as_uint(As[ar * 68 + k0]);
            unsigned int a1 = __float_as_uint(As[(ar + 8) * 68 + k0]);
            unsigned int a2 = __float_as_uint(As[ar * 68 + k1]);
            unsigned int a3 = __float_as_uint(As[(ar + 8) * 68 + k1]);
#pragma unroll
            for (int ns = 0; ns < 8; ns++) {
                int bc = ns * 8 + gid;
                unsigned int b0 = __float_as_uint(Bs[k0 * 72 + bc]);
                unsigned int b1 = __float_as_uint(Bs[k1 * 72 + bc]);
                MMA_TF32(c[ns], a0, a1, a2, a3, b0, b1);
            }
        }

#pragma unroll
        for (int ns = 0; ns < 8; ns++) {
            int col = n0 + ns * 8 + tg * 2;
            float b0 = bias[col], b1 = bias[col + 1];
            if (r0 < EE)
                *(__half2*)&g_ewh[(size_t)r0 * 4096 + col] =
                    __floats2half2_rn(c[ns][0] + b0, c[ns][1] + b1);
            if (r0 + 8 < EE)
                *(__half2*)&g_ewh[(size_t)(r0 + 8) * 4096 + col] =
                    __floats2half2_rn(c[ns][2] + b0, c[ns][3] + b1);
        }
    }
}

// ---------------- fused GRU gate GEMMs (tf32 x3): grid (79, 3, 2) --------------
// z=0: gi = relu(agg/cnt + bconv) @ W_ih^T + b_ih   (m computed inline from agg)
// z=1: gh = h @ W_hh^T + b_hh
#define GG_SMEM (2 * ((128 * 68) + (64 * 72)) * 4)

__global__ void __launch_bounds__(256) k_ggemm(const float* __restrict__ Wih,
                                               const float* __restrict__ bih,
                                               const float* __restrict__ Whh,
                                               const float* __restrict__ bhh,
                                               const float* __restrict__ bconv) {
    extern __shared__ float sm[];
    float* AsH = sm;                          // [128][68]
    float* BsH = sm + 128 * 68;               // [64 k][72 n]
    float* AsL = sm + 128 * 68 + 64 * 72;
    float* BsL = AsL + 128 * 68;

    const int tid = threadIdx.x;
    const int m0 = blockIdx.x * 128;
    const int n0 = blockIdx.y * 64;
    const int z  = blockIdx.z;
    const float* W    = z ? Whh : Wih;
    const float* bias = z ? bhh : bih;
    float* C          = z ? g_gh : g_gi;

    for (int idx = tid; idx < 128 * 64; idx += 256) {
        int r = idx >> 6, c = idx & 63;
        int gr = m0 + r;
        float v = 0.0f;
        if (gr < NN) {
            if (z) {
                v = g_out[gr * 64 + c];
            } else {
                float cnt = fmaxf(g_cnt[gr], 1.0f);
                v = fmaxf(g_agg[gr * 64 + c] / cnt + bconv[c], 0.0f);
            }
        }
        float hi = tf32r(v);
        AsH[r * 68 + c] = hi;
        AsL[r * 68 + c] = tf32r(v - hi);
    }
    for (int idx = tid; idx < 64 * 64; idx += 256) {
        int n = idx >> 6, k = idx & 63;
        float v = W[(n0 + n) * 64 + k];
        float hi = tf32r(v);
        BsH[k * 72 + n] = hi;
        BsL[k * 72 + n] = tf32r(v - hi);
    }
    __syncthreads();

    const int warp = tid >> 5, lane = tid & 31;
    const int gid = lane >> 2, tg = lane & 3;
    const int ar = warp * 16 + gid;

    float c[8][4];
#pragma unroll
    for (int i = 0; i < 8; i++)
#pragma unroll
        for (int j = 0; j < 4; j++) c[i][j] = 0.0f;

#pragma unroll
    for (int ks = 0; ks < 8; ks++) {
        int k0 = ks * 8 + tg, k1 = k0 + 4;
        unsigned int aH0 = __float_as_uint(AsH[ar * 68 + k0]);
        unsigned int aH1 = __float_as_uint(AsH[(ar + 8) * 68 + k0]);
        unsigned int aH2 = __float_as_uint(AsH[ar * 68 + k1]);
        unsigned int aH3 = __float_as_uint(AsH[(ar + 8) * 68 + k1]);
        unsigned int aL0 = __float_as_uint(AsL[ar * 68 + k0]);
        unsigned int aL1 = __float_as_uint(AsL[(ar + 8) * 68 + k0]);
        unsigned int aL2 = __float_as_uint(AsL[ar * 68 + k1]);
        unsigned int aL3 = __float_as_uint(AsL[(ar + 8) * 68 + k1]);
#pragma unroll
        for (int ns = 0; ns < 8; ns++) {
            int bc = ns * 8 + gid;
            unsigned int bH0 = __float_as_uint(BsH[k0 * 72 + bc]);
            unsigned int bH1 = __float_as_uint(BsH[k1 * 72 + bc]);
            unsigned int bL0 = __float_as_uint(BsL[k0 * 72 + bc]);
            unsigned int bL1 = __float_as_uint(BsL[k1 * 72 + bc]);
            MMA_TF32(c[ns], aH0, aH1, aH2, aH3, bL0, bL1);
            MMA_TF32(c[ns], aL0, aL1, aL2, aL3, bH0, bH1);
            MMA_TF32(c[ns], aH0, aH1, aH2, aH3, bH0, bH1);
        }
    }

    const int r0 = m0 + ar;
#pragma unroll
    for (int ns = 0; ns < 8; ns++) {
        int col = n0 + ns * 8 + tg * 2;
        float b0 = bias[col], b1 = bias[col + 1];
        if (r0 < NN)
            *(float2*)&C[(size_t)r0 * 192 + col] =
                make_float2(c[ns][0] + b0, c[ns][1] + b1);
        if (r0 + 8 < NN)
            *(float2*)&C[(size_t)(r0 + 8) * 192 + col] =
                make_float2(c[ns][2] + b0, c[ns][3] + b1);
    }
}

// ---------------- message passing ----------------
// 8 edges/block, 32 threads/edge, half2 per thread: fully coalesced 128B/row reads.
__global__ void k_msg() {
    __shared__ float os[8][64];
    int tid = threadIdx.x;
    int le = tid >> 5, lane = tid & 31;
    int e = blockIdx.x * 8 + le;               // grid 2500 => E exact
    int src = g_src[e];
    os[le][lane] = g_out[src * 64 + lane];
    os[le][lane + 32] = g_out[src * 64 + lane + 32];
    __syncthreads();
    const __half2* w = (const __half2*)g_ewh + (size_t)e * 2048 + lane;
    float s0 = 0.0f, s1 = 0.0f;
#pragma unroll 16
    for (int d = 0; d < 64; d++) {
        float2 v = __half22float2(w[(size_t)d * 32]);
        float o = os[le][d];
        s0 += o * v.x;
        s1 += o * v.y;
    }
    int dst = g_dst[e];
    atomicAdd(&g_agg[dst * 64 + 2 * lane], s0);
    atomicAdd(&g_agg[dst * 64 + 2 * lane + 1], s1);
}

// GRU pointwise; also resets agg for the next iteration (keeps zero invariant)
__global__ void k_grupt() {
    int i = blockIdx.x * 256 + threadIdx.x;    // grid 2500
    int n = i >> 6, j = i & 63;
    const float* gi = g_gi + n * 192;
    const float* gh = g_gh + n * 192;
    float r = sigf(gi[j] + gh[j]);
    float z = sigf(gi[64 + j] + gh[64 + j]);
    float t = tanhf(gi[128 + j] + r * gh[128 + j]);
    float h = g_out[i];
    g_out[i] = (1.0f - z) * t + z * h;
    g_agg[i] = 0.0f;
}

// ---------------- fused Set2Set (3 steps) + output MLP: one block per graph ----
__global__ void __launch_bounds__(256) k_set2set(
        const float* __restrict__ Wih, const float* __restrict__ bih,
        const float* __restrict__ Whh, const float* __restrict__ bhh,
        const float* __restrict__ W1, const float* __restrict__ b1,
        const float* __restrict__ W2, const float* __restrict__ b2,
        float* __restrict__ out) {
    int b = blockIdx.x, tid = threadIdx.x;     // grid 400, 256 thr
    int lo = g_off[b], hi = g_off[b + 1];
    __shared__ float qs[128], hs[64], cs[64], g[256], red[256], rpart[4][64];

    if (tid < 128) qs[tid] = 0.0f;
    if (tid < 64) { hs[tid] = 0.0f; cs[tid] = 0.0f; }
    __syncthreads();

    for (int st = 0; st < 3; st++) {
        // LSTM gates
        float acc = bih[tid] + bhh[tid];
        const float4* wi = (const float4*)(Wih + tid * 128);
#pragma unroll 8
        for (int k = 0; k < 32; k++) {
            float4 w = wi[k];
            acc += qs[4 * k] * w.x + qs[4 * k + 1] * w.y +
                   qs[4 * k + 2] * w.z + qs[4 * k + 3] * w.w;
        }
        const float4* wh = (const float4*)(Whh + tid * 64);
#pragma unroll 8
        for (int k = 0; k < 16; k++) {
            float4 w = wh[k];
            acc += hs[4 * k] * w.x + hs[4 * k + 1] * w.y +
                   hs[4 * k + 2] * w.z + hs[4 * k + 3] * w.w;
        }
        g[tid] = acc;
        __syncthreads();
        if (tid < 64) {
            float i_ = sigf(g[tid]);
            float f_ = sigf(g[64 + tid]);
            float gg = tanhf(g[128 + tid]);
            float o_ = sigf(g[192 + tid]);
            float c = f_ * cs[tid] + i_ * gg;
            cs[tid] = c;
            hs[tid] = o_ * tanhf(c);
        }
        __syncthreads();

        // e[n] = <out[n], q>
        {
            int warp = tid >> 5, lane = tid & 31;
            for (int n = lo + warp; n < hi; n += 8) {
                const float* o = g_out + n * 64;
                float v = o[lane] * hs[lane] + o[lane + 32] * hs[lane + 32];
#pragma unroll
                for (int s = 16; s > 0; s >>= 1) v += __shfl_xor_sync(0xffffffffu, v, s);
                if (lane == 0) g_e[n] = v;
            }
        }
        __syncthreads();

        // segment softmax over [lo,hi)
        float mx = -1e30f;
        for (int n = lo + tid; n < hi; n += 256) mx = fmaxf(mx, g_e[n]);
        red[tid] = mx; __syncthreads();
        for (int s = 128; s > 0; s >>= 1) {
            if (tid < s) red[tid] = fmaxf(red[tid], red[tid + s]);
            __syncthreads();
        }
        mx = red[0]; __syncthreads();

        float sm = 0.0f;
        for (int n = lo + tid; n < hi; n += 256) {
            float v = expf(g_e[n] - mx);
            g_e[n] = v;
            sm += v;
        }
        red[tid] = sm; __syncthreads();
        for (int s = 128; s > 0; s >>= 1) {
            if (tid < s) red[tid] += red[tid + s];
            __syncthreads();
        }
        float inv = (hi > lo) ? 1.0f / red[0] : 0.0f;
        __syncthreads();

        // r = sum a[n]*out[n]
        int f = tid & 63, c4 = tid >> 6;
        float r = 0.0f;
        for (int n = lo + c4; n < hi; n += 4) r += g_e[n] * g_out[n * 64 + f];
        rpart[c4][f] = r; __syncthreads();
        if (tid < 64) {
            qs[64 + tid] = (rpart[0][tid] + rpart[1][tid] +
                            rpart[2][tid] + rpart[3][tid]) * inv;
            qs[tid] = hs[tid];
        }
        __syncthreads();
    }

    // output MLP
    if (tid < 64) {
        float acc = b1[tid];
        const float4* w = (const float4*)(W1 + tid * 128);
#pragma unroll 8
        for (int k = 0; k < 32; k++) {
            float4 v = w[k];
            acc += qs[4 * k] * v.x + qs[4 * k + 1] * v.y +
                   qs[4 * k + 2] * v.z + qs[4 * k + 3] * v.w;
        }
        red[tid] = fmaxf(acc, 0.0f) * W2[tid];
    }
    __syncthreads();
    if (tid < 32) {
        float v = red[tid] + red[tid + 32];
#pragma unroll
        for (int s = 16; s > 0; s >>= 1) v += __shfl_down_sync(0xffffffffu, v, s);
        if (tid == 0) out[b] = v + b2[0];
    }
}

// ---------------- launch ----------------
extern "C" void kernel_launch(void* const* d_in, const int* in_sizes, int n_in,
                              void* d_out, int out_size) {
    const float* x      = (const float*)d_in[0];
    const float* ea     = (const float*)d_in[1];
    const float* W_in   = (const float*)d_in[2];
    const float* b_in   = (const float*)d_in[3];
    const float* W_e1   = (const float*)d_in[4];
    const float* b_e1   = (const float*)d_in[5];
    const float* W_e2   = (const float*)d_in[6];
    const float* b_e2   = (const float*)d_in[7];
    const float* b_conv = (const float*)d_in[8];
    const float* W_ih   = (const float*)d_in[9];
    const float* b_ih   = (const float*)d_in[10];
    const float* W_hh   = (const float*)d_in[11];
    const float* b_hh   = (const float*)d_in[12];
    const float* W_ihl  = (const float*)d_in[13];
    const float* b_ihl  = (const float*)d_in[14];
    const float* W_hhl  = (const float*)d_in[15];
    const float* b_hhl  = (const float*)d_in[16];
    const float* W_o1   = (const float*)d_in[17];
    const float* b_o1   = (const float*)d_in[18];
    const float* W_o2   = (const float*)d_in[19];
    const float* b_o2   = (const float*)d_in[20];
    const void*  ei     = d_in[21];
    const void*  bt     = d_in[22];
    float* out = (float*)d_out;

    cudaFuncSetAttribute(k_ewgemm, cudaFuncAttributeMaxDynamicSharedMemorySize, EW_SMEM);
    cudaFuncSetAttribute(k_ggemm, cudaFuncAttributeMaxDynamicSharedMemorySize, GG_SMEM);

    k_detect<<<40, 256>>>(ei);
    k_convert<<<128, 256>>>(ei, bt);
    k_proj<<<7502, 256>>>(x, W_in, b_in, ea, W_e1, b_e1);

    {
        dim3 grid((EE + 127) / 128, 4096 / 128);
        k_ewgemm<<<grid, 256, EW_SMEM>>>(W_e2, b_e2);
    }

    for (int it = 0; it < 3; it++) {
        k_msg<<<2500, 256>>>();
        {
            dim3 grid((NN + 127) / 128, 3, 2);
            k_ggemm<<<grid, 256, GG_SMEM>>>(W_ih, b_ih, W_hh, b_hh, b_conv);
        }
        k_grupt<<<2500, 256>>>();
    }

    k_set2set<<<BB, 256>>>(W_ihl, b_ihl, W_hhl, b_hhl, W_o1, b_o1, W_o2, b_o2, out);
}

// round 13
// speedup vs baseline: 1.0459x; 1.0459x over previous
#include <cuda_runtime.h>
#include <cuda_bf16.h>
#include <cuda_fp16.h>
#include <math.h>

#define NN 10000
#define EE 20000
#define BB 400

// ---------------- device scratch (static allocation only) ----------------
__device__ __half g_ewh[(size_t)EE * 4096]; // 163.8 MB edge-conditioned weights (fp16)
__device__ float g_he[EE * 64];             // edge hidden (MLP layer 1)
__device__ float g_out[NN * 64];            // node state (out == h)
__device__ float g_agg[NN * 64];            // scatter accumulator (kept zeroed)
__device__ float g_gi[NN * 192];            // GRU input gates
__device__ float g_gh[NN * 192];            // GRU hidden gates
__device__ float g_cnt[NN];
__device__ int   g_src[EE];
__device__ int   g_dst[EE];
__device__ int   g_batch[NN];
__device__ int   g_off[BB + 1];
__device__ float g_e[NN];
__device__ int   g_is64;

__device__ __forceinline__ float sigf(float x) { return 1.0f / (1.0f + expf(-x)); }

__device__ __forceinline__ float tf32r(float x) {
    unsigned int u;
    asm("cvt.rna.tf32.f32 %0, %1;" : "=r"(u) : "f"(x));
    return __uint_as_float(u);
}

#define MMA_TF32(C, A0, A1, A2, A3, B0, B1)                                          \
    asm volatile(                                                                    \
        "mma.sync.aligned.m16n8k8.row.col.f32.tf32.tf32.f32 "                        \
        "{%0,%1,%2,%3}, {%4,%5,%6,%7}, {%8,%9}, {%0,%1,%2,%3};"                      \
        : "+f"(C[0]), "+f"(C[1]), "+f"(C[2]), "+f"(C[3])                             \
        : "r"(A0), "r"(A1), "r"(A2), "r"(A3), "r"(B0), "r"(B1))

// ---------------- setup: dtype detect (parallel) + zero cnt ----------------
__global__ void k_detect(const void* ei) {
    // int64 little-endian: odd 32-bit words (high halves) all zero.
    // int32: odd words are random node indices in [0,10000): P(all zero) ~ 0.
    __shared__ int nz;
    if (blockIdx.x == 0) {
        if (threadIdx.x == 0) nz = 0;
        __syncthreads();
        if (threadIdx.x < 127) {
            const unsigned int* w = (const unsigned int*)ei;
            if (w[1 + 314 * threadIdx.x] != 0u) atomicOr(&nz, 1);
        }
        __syncthreads();
        if (threadIdx.x == 0) g_is64 = nz ? 0 : 1;
    }
    int i = blockIdx.x * 256 + threadIdx.x;      // grid 40 => 10240 >= NN
    if (i < NN) g_cnt[i] = 0.0f;
}

// convert indices, count in-degree, zero agg
__global__ void k_convert(const void* ei, const void* bt) {
    int i = blockIdx.x * blockDim.x + threadIdx.x;
    int stride = gridDim.x * blockDim.x;
    int is64 = g_is64;
    for (int e = i; e < EE; e += stride) {
        int s, d;
        if (is64) {
            const long long* p = (const long long*)ei;
            s = (int)p[e]; d = (int)p[EE + e];
        } else {
            const int* p = (const int*)ei;
            s = p[e]; d = p[EE + e];
        }
        g_src[e] = s; g_dst[e] = d;
        atomicAdd(&g_cnt[d], 1.0f);             // g_cnt zeroed by k_detect (prior launch)
    }
    for (int n = i; n < NN; n += stride) {
        int b;
        if (is64) b = (int)((const long long*)bt)[n];
        else      b = ((const int*)bt)[n];
        g_batch[n] = b;
    }
    for (int j = i; j < NN * 64; j += stride) g_agg[j] = 0.0f;
}

// ---------------- fused projections + segment offsets -----------------------
// blocks [0,2500): node proj; [2500,7500): edge proj; [7500,7502): offsets
__global__ void k_proj(const float* __restrict__ x, const float* __restrict__ Wn,
                       const float* __restrict__ bn, const float* __restrict__ ea,
                       const float* __restrict__ We, const float* __restrict__ be) {
    __shared__ float Ws[64 * 33];
    int tid = threadIdx.x;
    if (blockIdx.x < 2500) {
        // node: out = relu(x @ Wn^T + bn), x[N,32]
        for (int idx = tid; idx < 64 * 32; idx += 256)
            Ws[(idx >> 5) * 33 + (idx & 31)] = Wn[idx];
        __syncthreads();
        int i = blockIdx.x * 256 + tid;          // 2500*256 == N*64 exact
        int n = i >> 6, j = i & 63;
        const float* xr = x + n * 32;
        float acc = bn[j];
#pragma unroll
        for (int k = 0; k < 32; k++) acc += xr[k] * Ws[j * 33 + k];
        g_out[i] = fmaxf(acc, 0.0f);
    } else if (blockIdx.x < 7500) {
        // edge: he = relu(ea @ We^T + be), ea[E,16]
        for (int idx = tid; idx < 64 * 16; idx += 256)
            Ws[(idx >> 4) * 17 + (idx & 15)] = We[idx];
        __syncthreads();
        int i = (blockIdx.x - 2500) * 256 + tid; // 5000*256 == E*64 exact
        int e = i >> 6, j = i & 63;
        const float* er = ea + e * 16;
        float acc = be[j];
#pragma unroll
        for (int k = 0; k < 16; k++) acc += er[k] * Ws[j * 17 + k];
        g_he[i] = fmaxf(acc, 0.0f);
    } else {
        // segment offsets via binary search on sorted batch
        int b = (blockIdx.x - 7500) * 256 + tid;
        if (b <= BB) {
            int lo = 0, hi = NN;
            while (lo < hi) {
                int mid = (lo + hi) >> 1;
                if (g_batch[mid] < b) lo = mid + 1; else hi = mid;
            }
            g_off[b] = lo;
        }
    }
}

// ---------------- ew GEMM: g_ewh[E,4096] = he @ W_e2^T + b_e2 (tf32 x1, fp16 out)
// Block: 128 M-rows x 128 N-cols (two sequential 64-col B tiles over one A tile).
// B smem layout is [n][k] pitch 68: B-fragment loads are bank-conflict-free
// (bank = 4*gid + tg + const = lane-distinct). The previous [k][n] pitch-72
// layout had an 8-way conflict (bank = 8*(tg+gid) mod 32) -> L1 84% bound.
#define EW_SMEM (((128 * 68) + (64 * 68)) * 4)

__global__ void __launch_bounds__(256) k_ewgemm(const float* __restrict__ W,
                                                const float* __restrict__ bias) {
    extern __shared__ float sm[];
    float* As = sm;                    // [128 r][68]
    float* Bs = sm + 128 * 68;         // [64 n][68 k]

    const int tid = threadIdx.x;
    const int m0 = blockIdx.x * 128;
    const int warp = tid >> 5, lane = tid & 31;
    const int gid = lane >> 2, tg = lane & 3;
    const int ar = warp * 16 + gid;
    const int r0 = m0 + ar;

    for (int idx = tid; idx < 128 * 64; idx += 256) {
        int r = idx >> 6, c = idx & 63;
        int gr = m0 + r;
        float v = (gr < EE) ? g_he[gr * 64 + c] : 0.0f;
        As[r * 68 + c] = tf32r(v);
    }

    for (int half = 0; half < 2; half++) {
        const int n0 = blockIdx.y * 128 + half * 64;
        __syncthreads();               // A ready (half 0); prior compute done (half 1)
        for (int idx = tid; idx < 64 * 64; idx += 256) {
            int n = idx >> 6, k = idx & 63;
            Bs[n * 68 + k] = tf32r(W[(n0 + n) * 64 + k]);
        }
        __syncthreads();

        float c[8][4];
#pragma unroll
        for (int i = 0; i < 8; i++)
#pragma unroll
            for (int j = 0; j < 4; j++) c[i][j] = 0.0f;

#pragma unroll
        for (int ks = 0; ks < 8; ks++) {
            int k0 = ks * 8 + tg, k1 = k0 + 4;
            unsigned int a0 = __float_as_uint(As[ar * 68 + k0]);
            unsigned int a1 = __float_as_uint(As[(ar + 8) * 68 + k0]);
            unsigned int a2 = __float_as_uint(As[ar * 68 + k1]);
            unsigned int a3 = __float_as_uint(As[(ar + 8) * 68 + k1]);
#pragma unroll
            for (int ns = 0; ns < 8; ns++) {
                int bc = ns * 8 + gid;
                unsigned int b0 = __float_as_uint(Bs[bc * 68 + k0]);
                unsigned int b1 = __float_as_uint(Bs[bc * 68 + k1]);
                MMA_TF32(c[ns], a0, a1, a2, a3, b0, b1);
            }
        }

#pragma unroll
        for (int ns = 0; ns < 8; ns++) {
            int col = n0 + ns * 8 + tg * 2;
            float b0 = bias[col], b1 = bias[col + 1];
            if (r0 < EE)
                *(__half2*)&g_ewh[(size_t)r0 * 4096 + col] =
                    __floats2half2_rn(c[ns][0] + b0, c[ns][1] + b1);
            if (r0 + 8 < EE)
                *(__half2*)&g_ewh[(size_t)(r0 + 8) * 4096 + col] =
                    __floats2half2_rn(c[ns][2] + b0, c[ns][3] + b1);
        }
    }
}

// ---------------- fused GRU gate GEMMs (tf32 x3): grid (79, 3, 2) --------------
// z=0: gi = relu(agg/cnt + bconv) @ W_ih^T + b_ih   (m computed inline from agg)
// z=1: gh = h @ W_hh^T + b_hh
// B smem layout [n][k] pitch 68 (conflict-free, see k_ewgemm).
#define GG_SMEM ((2 * 128 * 68 + 2 * 64 * 68) * 4)

__global__ void __launch_bounds__(256) k_ggemm(const float* __restrict__ Wih,
                                               const float* __restrict__ bih,
                                               const float* __restrict__ Whh,
                                               const float* __restrict__ bhh,
                                               const float* __restrict__ bconv) {
    extern __shared__ float sm[];
    float* AsH = sm;                          // [128][68]
    float* AsL = sm + 128 * 68;
    float* BsH = sm + 2 * 128 * 68;           // [64 n][68 k]
    float* BsL = BsH + 64 * 68;

    const int tid = threadIdx.x;
    const int m0 = blockIdx.x * 128;
    const int n0 = blockIdx.y * 64;
    const int z  = blockIdx.z;
    const float* W    = z ? Whh : Wih;
    const float* bias = z ? bhh : bih;
    float* C          = z ? g_gh : g_gi;

    for (int idx = tid; idx < 128 * 64; idx += 256) {
        int r = idx >> 6, c = idx & 63;
        int gr = m0 + r;
        float v = 0.0f;
        if (gr < NN) {
            if (z) {
                v = g_out[gr * 64 + c];
            } else {
                float cnt = fmaxf(g_cnt[gr], 1.0f);
                v = fmaxf(g_agg[gr * 64 + c] / cnt + bconv[c], 0.0f);
            }
        }
        float hi = tf32r(v);
        AsH[r * 68 + c] = hi;
        AsL[r * 68 + c] = tf32r(v - hi);
    }
    for (int idx = tid; idx < 64 * 64; idx += 256) {
        int n = idx >> 6, k = idx & 63;
        float v = W[(n0 + n) * 64 + k];
        float hi = tf32r(v);
        BsH[n * 68 + k] = hi;
        BsL[n * 68 + k] = tf32r(v - hi);
    }
    __syncthreads();

    const int warp = tid >> 5, lane = tid & 31;
    const int gid = lane >> 2, tg = lane & 3;
    const int ar = warp * 16 + gid;

    float c[8][4];
#pragma unroll
    for (int i = 0; i < 8; i++)
#pragma unroll
        for (int j = 0; j < 4; j++) c[i][j] = 0.0f;

#pragma unroll
    for (int ks = 0; ks < 8; ks++) {
        int k0 = ks * 8 + tg, k1 = k0 + 4;
        unsigned int aH0 = __float_as_uint(AsH[ar * 68 + k0]);
        unsigned int aH1 = __float_as_uint(AsH[(ar + 8) * 68 + k0]);
        unsigned int aH2 = __float_as_uint(AsH[ar * 68 + k1]);
        unsigned int aH3 = __float_as_uint(AsH[(ar + 8) * 68 + k1]);
        unsigned int aL0 = __float_as_uint(AsL[ar * 68 + k0]);
        unsigned int aL1 = __float_as_uint(AsL[(ar + 8) * 68 + k0]);
        unsigned int aL2 = __float_as_uint(AsL[ar * 68 + k1]);
        unsigned int aL3 = __float_as_uint(AsL[(ar + 8) * 68 + k1]);
#pragma unroll
        for (int ns = 0; ns < 8; ns++) {
            int bc = ns * 8 + gid;
            unsigned int bH0 = __float_as_uint(BsH[bc * 68 + k0]);
            unsigned int bH1 = __float_as_uint(BsH[bc * 68 + k1]);
            unsigned int bL0 = __float_as_uint(BsL[bc * 68 + k0]);
            unsigned int bL1 = __float_as_uint(BsL[bc * 68 + k1]);
            MMA_TF32(c[ns], aH0, aH1, aH2, aH3, bL0, bL1);
            MMA_TF32(c[ns], aL0, aL1, aL2, aL3, bH0, bH1);
            MMA_TF32(c[ns], aH0, aH1, aH2, aH3, bH0, bH1);
        }
    }

    const int r0 = m0 + ar;
#pragma unroll
    for (int ns = 0; ns < 8; ns++) {
        int col = n0 + ns * 8 + tg * 2;
        float b0 = bias[col], b1 = bias[col + 1];
        if (r0 < NN)
            *(float2*)&C[(size_t)r0 * 192 + col] =
                make_float2(c[ns][0] + b0, c[ns][1] + b1);
        if (r0 + 8 < NN)
            *(float2*)&C[(size_t)(r0 + 8) * 192 + col] =
                make_float2(c[ns][2] + b0, c[ns][3] + b1);
    }
}

// ---------------- message passing ----------------
// 8 edges/block, 32 threads/edge, half2 per thread: fully coalesced 128B/row reads.
__global__ void k_msg() {
    __shared__ float os[8][64];
    int tid = threadIdx.x;
    int le = tid >> 5, lane = tid & 31;
    int e = blockIdx.x * 8 + le;               // grid 2500 => E exact
    int src = g_src[e];
    os[le][lane] = g_out[src * 64 + lane];
    os[le][lane + 32] = g_out[src * 64 + lane + 32];
    __syncthreads();
    const __half2* w = (const __half2*)g_ewh + (size_t)e * 2048 + lane;
    float s0 = 0.0f, s1 = 0.0f;
#pragma unroll 16
    for (int d = 0; d < 64; d++) {
        float2 v = __half22float2(w[(size_t)d * 32]);
        float o = os[le][d];
        s0 += o * v.x;
        s1 += o * v.y;
    }
    int dst = g_dst[e];
    atomicAdd(&g_agg[dst * 64 + 2 * lane], s0);
    atomicAdd(&g_agg[dst * 64 + 2 * lane + 1], s1);
}

// GRU pointwise; also resets agg for the next iteration (keeps zero invariant)
__global__ void k_grupt() {
    int i = blockIdx.x * 256 + threadIdx.x;    // grid 2500
    int n = i >> 6, j = i & 63;
    const float* gi = g_gi + n * 192;
    const float* gh = g_gh + n * 192;
    float r = sigf(gi[j] + gh[j]);
    float z = sigf(gi[64 + j] + gh[64 + j]);
    float t = tanhf(gi[128 + j] + r * gh[128 + j]);
    float h = g_out[i];
    g_out[i] = (1.0f - z) * t + z * h;
    g_agg[i] = 0.0f;
}

// ---------------- fused Set2Set (3 steps) + output MLP: one block per graph ----
__global__ void __launch_bounds__(256) k_set2set(
        const float* __restrict__ Wih, const float* __restrict__ bih,
        const float* __restrict__ Whh, const float* __restrict__ bhh,
        const float* __restrict__ W1, const float* __restrict__ b1,
        const float* __restrict__ W2, const float* __restrict__ b2,
        float* __restrict__ out) {
    int b = blockIdx.x, tid = threadIdx.x;     // grid 400, 256 thr
    int lo = g_off[b], hi = g_off[b + 1];
    __shared__ float qs[128], hs[64], cs[64], g[256], red[256], rpart[4][64];

    if (tid < 128) qs[tid] = 0.0f;
    if (tid < 64) { hs[tid] = 0.0f; cs[tid] = 0.0f; }
    __syncthreads();

    for (int st = 0; st < 3; st++) {
        // LSTM gates
        float acc = bih[tid] + bhh[tid];
        const float4* wi = (const float4*)(Wih + tid * 128);
#pragma unroll 8
        for (int k = 0; k < 32; k++) {
            float4 w = wi[k];
            acc += qs[4 * k] * w.x + qs[4 * k + 1] * w.y +
                   qs[4 * k + 2] * w.z + qs[4 * k + 3] * w.w;
        }
        const float4* wh = (const float4*)(Whh + tid * 64);
#pragma unroll 8
        for (int k = 0; k < 16; k++) {
            float4 w = wh[k];
            acc += hs[4 * k] * w.x + hs[4 * k + 1] * w.y +
                   hs[4 * k + 2] * w.z + hs[4 * k + 3] * w.w;
        }
        g[tid] = acc;
        __syncthreads();
        if (tid < 64) {
            float i_ = sigf(g[tid]);
            float f_ = sigf(g[64 + tid]);
            float gg = tanhf(g[128 + tid]);
            float o_ = sigf(g[192 + tid]);
            float c = f_ * cs[tid] + i_ * gg;
            cs[tid] = c;
            hs[tid] = o_ * tanhf(c);
        }
        __syncthreads();

        // e[n] = <out[n], q>
        {
            int warp = tid >> 5, lane = tid & 31;
            for (int n = lo + warp; n < hi; n += 8) {
                const float* o = g_out + n * 64;
                float v = o[lane] * hs[lane] + o[lane + 32] * hs[lane + 32];
#pragma unroll
                for (int s = 16; s > 0; s >>= 1) v += __shfl_xor_sync(0xffffffffu, v, s);
                if (lane == 0) g_e[n] = v;
            }
        }
        __syncthreads();

        // segment softmax over [lo,hi)
        float mx = -1e30f;
        for (int n = lo + tid; n < hi; n += 256) mx = fmaxf(mx, g_e[n]);
        red[tid] = mx; __syncthreads();
        for (int s = 128; s > 0; s >>= 1) {
            if (tid < s) red[tid] = fmaxf(red[tid], red[tid + s]);
            __syncthreads();
        }
        mx = red[0]; __syncthreads();

        float sm = 0.0f;
        for (int n = lo + tid; n < hi; n += 256) {
            float v = expf(g_e[n] - mx);
            g_e[n] = v;
            sm += v;
        }
        red[tid] = sm; __syncthreads();
        for (int s = 128; s > 0; s >>= 1) {
            if (tid < s) red[tid] += red[tid + s];
            __syncthreads();
        }
        float inv = (hi > lo) ? 1.0f / red[0] : 0.0f;
        __syncthreads();

        // r = sum a[n]*out[n]
        int f = tid & 63, c4 = tid >> 6;
        float r = 0.0f;
        for (int n = lo + c4; n < hi; n += 4) r += g_e[n] * g_out[n * 64 + f];
        rpart[c4][f] = r; __syncthreads();
        if (tid < 64) {
            qs[64 + tid] = (rpart[0][tid] + rpart[1][tid] +
                            rpart[2][tid] + rpart[3][tid]) * inv;
            qs[tid] = hs[tid];
        }
        __syncthreads();
    }

    // output MLP
    if (tid < 64) {
        float acc = b1[tid];
        const float4* w = (const float4*)(W1 + tid * 128);
#pragma unroll 8
        for (int k = 0; k < 32; k++) {
            float4 v = w[k];
            acc += qs[4 * k] * v.x + qs[4 * k + 1] * v.y +
                   qs[4 * k + 2] * v.z + qs[4 * k + 3] * v.w;
        }
        red[tid] = fmaxf(acc, 0.0f) * W2[tid];
    }
    __syncthreads();
    if (tid < 32) {
        float v = red[tid] + red[tid + 32];
#pragma unroll
        for (int s = 16; s > 0; s >>= 1) v += __shfl_down_sync(0xffffffffu, v, s);
        if (tid == 0) out[b] = v + b2[0];
    }
}

// ---------------- launch ----------------
extern "C" void kernel_launch(void* const* d_in, const int* in_sizes, int n_in,
                              void* d_out, int out_size) {
    const float* x      = (const float*)d_in[0];
    const float* ea     = (const float*)d_in[1];
    const float* W_in   = (const float*)d_in[2];
    const float* b_in   = (const float*)d_in[3];
    const float* W_e1   = (const float*)d_in[4];
    const float* b_e1   = (const float*)d_in[5];
    const float* W_e2   = (const float*)d_in[6];
    const float* b_e2   = (const float*)d_in[7];
    const float* b_conv = (const float*)d_in[8];
    const float* W_ih   = (const float*)d_in[9];
    const float* b_ih   = (const float*)d_in[10];
    const float* W_hh   = (const float*)d_in[11];
    const float* b_hh   = (const float*)d_in[12];
    const float* W_ihl  = (const float*)d_in[13];
    const float* b_ihl  = (const float*)d_in[14];
    const float* W_hhl  = (const float*)d_in[15];
    const float* b_hhl  = (const float*)d_in[16];
    const float* W_o1   = (const float*)d_in[17];
    const float* b_o1   = (const float*)d_in[18];
    const float* W_o2   = (const float*)d_in[19];
    const float* b_o2   = (const float*)d_in[20];
    const void*  ei     = d_in[21];
    const void*  bt     = d_in[22];
    float* out = (float*)d_out;

    cudaFuncSetAttribute(k_ewgemm, cudaFuncAttributeMaxDynamicSharedMemorySize, EW_SMEM);
    cudaFuncSetAttribute(k_ggemm, cudaFuncAttributeMaxDynamicSharedMemorySize, GG_SMEM);

    k_detect<<<40, 256>>>(ei);
    k_convert<<<128, 256>>>(ei, bt);
    k_proj<<<7502, 256>>>(x, W_in, b_in, ea, W_e1, b_e1);

    {
        dim3 grid((EE + 127) / 128, 4096 / 128);
        k_ewgemm<<<grid, 256, EW_SMEM>>>(W_e2, b_e2);
    }

    for (int it = 0; it < 3; it++) {
        k_msg<<<2500, 256>>>();
        {
            dim3 grid((NN + 127) / 128, 3, 2);
            k_ggemm<<<grid, 256, GG_SMEM>>>(W_ih, b_ih, W_hh, b_hh, b_conv);
        }
        k_grupt<<<2500, 256>>>();
    }

    k_set2set<<<BB, 256>>>(W_ihl, b_ihl, W_hhl, b_hhl, W_o1, b_o1, W_o2, b_o2, out);
}